// round 1
// baseline (speedup 1.0000x reference)
#include <cuda_runtime.h>

// ComposeTransform: out[b] = trilinear(disp1[b], grid + disp2[b]) + disp2[b]
// vol shape per batch: [D,H,W,3], D=160, H=192, W=160.

#define DD 160
#define HH 192
#define WW 160
#define VOX (DD * HH * WW)

__global__ __launch_bounds__(256)
void compose_kernel(const float* __restrict__ d1,
                    const float* __restrict__ d2,
                    float* __restrict__ out,
                    int total)  // total voxels over both batches
{
    int idx = blockIdx.x * blockDim.x + threadIdx.x;
    if (idx >= total) return;

    int b = idx / VOX;
    int r = idx - b * VOX;
    int x = r / (HH * WW);
    int rem = r - x * (HH * WW);
    int y = rem / WW;
    int z = rem - y * WW;

    // load displacement 2 (3 contiguous floats)
    const float* p2 = d2 + (size_t)idx * 3;
    float dx = p2[0];
    float dy = p2[1];
    float dz = p2[2];

    float lx = (float)x + dx;
    float ly = (float)y + dy;
    float lz = (float)z + dz;

    // floor corners
    float fx = floorf(lx);
    float fy = floorf(ly);
    float fz = floorf(lz);

    // clipped floor / ceil corners (match reference semantics exactly)
    float i0x = fminf(fmaxf(fx, 0.0f), (float)(DD - 1));
    float i0y = fminf(fmaxf(fy, 0.0f), (float)(HH - 1));
    float i0z = fminf(fmaxf(fz, 0.0f), (float)(WW - 1));
    float i1x = fminf(fmaxf(fx + 1.0f, 0.0f), (float)(DD - 1));
    float i1y = fminf(fmaxf(fy + 1.0f, 0.0f), (float)(HH - 1));
    float i1z = fminf(fmaxf(fz + 1.0f, 0.0f), (float)(WW - 1));

    // weight attached to floor corner = clip(ceil_clipped - loc, 0, 1)
    float wfx = fminf(fmaxf(i1x - lx, 0.0f), 1.0f);
    float wfy = fminf(fmaxf(i1y - ly, 0.0f), 1.0f);
    float wfz = fminf(fmaxf(i1z - lz, 0.0f), 1.0f);
    float wcx = 1.0f - wfx;
    float wcy = 1.0f - wfy;
    float wcz = 1.0f - wfz;

    int ix0 = (int)i0x, iy0 = (int)i0y, iz0 = (int)i0z;
    int ix1 = (int)i1x, iy1 = (int)i1y, iz1 = (int)i1z;

    const float* v = d1 + (size_t)b * (size_t)VOX * 3;

    // row base offsets (flat voxel index * 3)
    size_t row00 = ((size_t)(ix0 * HH + iy0) * WW) * 3;
    size_t row01 = ((size_t)(ix0 * HH + iy1) * WW) * 3;
    size_t row10 = ((size_t)(ix1 * HH + iy0) * WW) * 3;
    size_t row11 = ((size_t)(ix1 * HH + iy1) * WW) * 3;
    size_t z0 = (size_t)iz0 * 3;
    size_t z1 = (size_t)iz1 * 3;

    float w000 = wfx * wfy * wfz;
    float w001 = wfx * wfy * wcz;
    float w010 = wfx * wcy * wfz;
    float w011 = wfx * wcy * wcz;
    float w100 = wcx * wfy * wfz;
    float w101 = wcx * wfy * wcz;
    float w110 = wcx * wcy * wfz;
    float w111 = wcx * wcy * wcz;

    const float* c000 = v + row00 + z0;
    const float* c001 = v + row00 + z1;
    const float* c010 = v + row01 + z0;
    const float* c011 = v + row01 + z1;
    const float* c100 = v + row10 + z0;
    const float* c101 = v + row10 + z1;
    const float* c110 = v + row11 + z0;
    const float* c111 = v + row11 + z1;

    float a0 = 0.0f, a1 = 0.0f, a2 = 0.0f;
    a0 = fmaf(w000, c000[0], a0); a1 = fmaf(w000, c000[1], a1); a2 = fmaf(w000, c000[2], a2);
    a0 = fmaf(w001, c001[0], a0); a1 = fmaf(w001, c001[1], a1); a2 = fmaf(w001, c001[2], a2);
    a0 = fmaf(w010, c010[0], a0); a1 = fmaf(w010, c010[1], a1); a2 = fmaf(w010, c010[2], a2);
    a0 = fmaf(w011, c011[0], a0); a1 = fmaf(w011, c011[1], a1); a2 = fmaf(w011, c011[2], a2);
    a0 = fmaf(w100, c100[0], a0); a1 = fmaf(w100, c100[1], a1); a2 = fmaf(w100, c100[2], a2);
    a0 = fmaf(w101, c101[0], a0); a1 = fmaf(w101, c101[1], a1); a2 = fmaf(w101, c101[2], a2);
    a0 = fmaf(w110, c110[0], a0); a1 = fmaf(w110, c110[1], a1); a2 = fmaf(w110, c110[2], a2);
    a0 = fmaf(w111, c111[0], a0); a1 = fmaf(w111, c111[1], a1); a2 = fmaf(w111, c111[2], a2);

    float* po = out + (size_t)idx * 3;
    po[0] = a0 + dx;
    po[1] = a1 + dy;
    po[2] = a2 + dz;
}

extern "C" void kernel_launch(void* const* d_in, const int* in_sizes, int n_in,
                              void* d_out, int out_size) {
    const float* d1 = (const float*)d_in[0];
    const float* d2 = (const float*)d_in[1];
    float* out = (float*)d_out;
    int total = in_sizes[1] / 3;  // voxels across both batches
    int threads = 256;
    int blocks = (total + threads - 1) / threads;
    compose_kernel<<<blocks, threads>>>(d1, d2, out, total);
}

// round 2
// speedup vs baseline: 1.2318x; 1.2318x over previous
#include <cuda_runtime.h>

// ComposeTransform: out[b] = trilinear(disp1[b], grid + disp2[b]) + disp2[b]
// vol shape per batch: [D,H,W,3], D=160, H=192, W=160.
// One thread per (voxel, channel): lane triplets share a voxel, each gathers
// only its own channel -> 8 scalar gather LDGs/thread with ~1/3 the per-warp
// address footprint of the one-voxel-per-thread version.

#define DD 160
#define HH 192
#define WW 160
#define VOX (DD * HH * WW)

__global__ __launch_bounds__(384)
void compose_kernel(const float* __restrict__ d1,
                    const float* __restrict__ d2,
                    float* __restrict__ out,
                    int n)  // total elements = voxels * 3
{
    int t = blockIdx.x * blockDim.x + threadIdx.x;
    if (t >= n) return;

    int v  = t / 3;          // voxel index (global, includes batch)
    int ch = t - v * 3;      // channel 0..2

    int b = v / VOX;
    int r = v - b * VOX;
    int x = r / (HH * WW);
    int rem = r - x * (HH * WW);
    int y = rem / WW;
    int z = rem - y * WW;

    // displacement 2 at this voxel (3 lanes of a triplet hit the same line)
    const float* p2 = d2 + (size_t)v * 3;
    float dx = __ldg(p2 + 0);
    float dy = __ldg(p2 + 1);
    float dz = __ldg(p2 + 2);

    float lx = (float)x + dx;
    float ly = (float)y + dy;
    float lz = (float)z + dz;

    float fx = floorf(lx);
    float fy = floorf(ly);
    float fz = floorf(lz);

    // clipped floor / ceil corners (reference semantics)
    float i0x = fminf(fmaxf(fx, 0.0f), (float)(DD - 1));
    float i0y = fminf(fmaxf(fy, 0.0f), (float)(HH - 1));
    float i0z = fminf(fmaxf(fz, 0.0f), (float)(WW - 1));
    float i1x = fminf(fmaxf(fx + 1.0f, 0.0f), (float)(DD - 1));
    float i1y = fminf(fmaxf(fy + 1.0f, 0.0f), (float)(HH - 1));
    float i1z = fminf(fmaxf(fz + 1.0f, 0.0f), (float)(WW - 1));

    // weight attached to floor corner = clip(ceil_clipped - loc, 0, 1)
    float wfx = fminf(fmaxf(i1x - lx, 0.0f), 1.0f);
    float wfy = fminf(fmaxf(i1y - ly, 0.0f), 1.0f);
    float wfz = fminf(fmaxf(i1z - lz, 0.0f), 1.0f);
    float wcx = 1.0f - wfx;
    float wcy = 1.0f - wfy;
    float wcz = 1.0f - wfz;

    int ix0 = (int)i0x, iy0 = (int)i0y, iz0 = (int)i0z;
    int ix1 = (int)i1x, iy1 = (int)i1y, iz1 = (int)i1z;

    const float* vbase = d1 + (size_t)b * (size_t)VOX * 3 + ch;

    int row00 = (ix0 * HH + iy0) * WW;
    int row01 = (ix0 * HH + iy1) * WW;
    int row10 = (ix1 * HH + iy0) * WW;
    int row11 = (ix1 * HH + iy1) * WW;

    float w00z0 = wfx * wfy * wfz;
    float w00z1 = wfx * wfy * wcz;
    float w01z0 = wfx * wcy * wfz;
    float w01z1 = wfx * wcy * wcz;
    float w10z0 = wcx * wfy * wfz;
    float w10z1 = wcx * wfy * wcz;
    float w11z0 = wcx * wcy * wfz;
    float w11z1 = wcx * wcy * wcz;

    float acc;
    acc  = w00z0 * __ldg(vbase + (size_t)(row00 + iz0) * 3);
    acc  = fmaf(w00z1, __ldg(vbase + (size_t)(row00 + iz1) * 3), acc);
    acc  = fmaf(w01z0, __ldg(vbase + (size_t)(row01 + iz0) * 3), acc);
    acc  = fmaf(w01z1, __ldg(vbase + (size_t)(row01 + iz1) * 3), acc);
    acc  = fmaf(w10z0, __ldg(vbase + (size_t)(row10 + iz0) * 3), acc);
    acc  = fmaf(w10z1, __ldg(vbase + (size_t)(row10 + iz1) * 3), acc);
    acc  = fmaf(w11z0, __ldg(vbase + (size_t)(row11 + iz0) * 3), acc);
    acc  = fmaf(w11z1, __ldg(vbase + (size_t)(row11 + iz1) * 3), acc);

    // add this channel's d2 component
    float d2c = (ch == 0) ? dx : ((ch == 1) ? dy : dz);
    out[t] = acc + d2c;
}

extern "C" void kernel_launch(void* const* d_in, const int* in_sizes, int n_in,
                              void* d_out, int out_size) {
    const float* d1 = (const float*)d_in[0];
    const float* d2 = (const float*)d_in[1];
    float* out = (float*)d_out;
    int n = in_sizes[1];  // total elements (voxels * 3)
    int threads = 384;
    int blocks = (n + threads - 1) / threads;
    compose_kernel<<<blocks, threads>>>(d1, d2, out, n);
}